// round 13
// baseline (speedup 1.0000x reference)
#include <cuda_runtime.h>

// RSI fused single pass, v13 = v8 + one subtractive edit. out[c] = g/(g+l)
// over 13-wide window of positive/negative relative deltas (0 if no losses).
//
// v8 skeleton verbatim (best: 29.44us): TPB=256, lane31 guarded LDG for x16,
// smem p-exchange, S-slide + exact L-prefix window loop, transpose stores.
// Single change: publish p[0..11] only (p[12..15] never read by neighbors)
// -> 3 STS.128 instead of 4.
// Lessons kept: no shuffle exchange (R7/R12), no launch_bounds cap (R9), no
// alignment-phase store specialization (R10/R11), TPB=256 not 128 (R12).

#define NROWS  2048
#define NCOLS  8192
#define TPB    256
#define ITEMS  16
#define WTILE  512               // outputs per warp
#define TILE   4096              // outputs per block
#define MAXW   64
#define SLOT   20                // smem floats per lane slot (16 data + 4 pad)
#define PREG   (SLOT * 33)       // 32 lanes + halo slot

__global__ __launch_bounds__(TPB) void rsi_v13(
    const float* __restrict__ in,
    float* __restrict__ out,
    int out_cols)
{
    __shared__ __align__(16) float s_p[8 * PREG];

    const int tid   = threadIdx.x;
    const int lane  = tid & 31;
    const int wrp   = tid >> 5;
    const int row   = blockIdx.y;
    const int wbase = blockIdx.x * TILE + wrp * WTILE;   // warp's first column
    const float* rin = in + (size_t)row * NCOLS;
    float* pw = s_p + wrp * PREG;
    float* myslot = pw + SLOT * lane;

    const bool edge = (wbase + WTILE) >= NCOLS;          // last warp of the row

    // ---- load own 16 inputs (wbase+512 <= 8192: always in-row) ----
    const int g0 = wbase + ITEMS * lane;
    const float4 xA = *(const float4*)(rin + g0);
    const float4 xB = *(const float4*)(rin + g0 + 4);
    const float4 xC = *(const float4*)(rin + g0 + 8);
    const float4 xD = *(const float4*)(rin + g0 + 12);

    // x[g0+16]: neighbor's first x via shuffle; lane 31 loads (guarded)
    float x16 = __shfl_down_sync(0xffffffffu, xA.x, 1);
    if (lane == 31)
        x16 = (!edge) ? rin[g0 + 16] : 0.0f;

    // halo x: lanes 0..12 load x[wbase+512+lane] (zero past row end)
    float xe = 0.0f;
    if (lane < 13) {
        const int ge = wbase + WTILE + lane;
        xe = (ge < NCOLS) ? rin[ge] : 0.0f;
    }
    const float xen = __shfl_down_sync(0xffffffffu, xe, 1);

    // ---- own 16 p-values ----
    const float xs[17] = {xA.x, xA.y, xA.z, xA.w, xB.x, xB.y, xB.z, xB.w,
                          xC.x, xC.y, xC.z, xC.w, xD.x, xD.y, xD.z, xD.w, x16};
    float p[ITEMS];
    #pragma unroll
    for (int c = 0; c < ITEMS; ++c) {
        const float prev = xs[c];
        p[c] = (prev != 0.0f) ? __fdividef(xs[c + 1] - prev, prev) : 0.0f;
    }

    // ---- publish p[0..11] (p[12..15] never read by neighbors) ----
    *(float4*)(myslot)     = make_float4(p[0], p[1], p[2],  p[3]);
    *(float4*)(myslot + 4) = make_float4(p[4], p[5], p[6],  p[7]);
    *(float4*)(myslot + 8) = make_float4(p[8], p[9], p[10], p[11]);
    if (lane < 12) {                                     // halo p -> slot 32
        const float pe = (xe != 0.0f) ? __fdividef(xen - xe, xe) : 0.0f;
        pw[SLOT * 32 + lane] = pe;
    }
    __syncwarp();

    // ---- fetch 12 neighbor p-values (lane 31 hits halo slot 32) ----
    const float* nb = pw + SLOT * (lane + 1);
    const float4 n0 = *(const float4*)(nb);
    const float4 n1 = *(const float4*)(nb + 4);
    const float4 n2 = *(const float4*)(nb + 8);
    __syncwarp();                                        // reads done before overwrite

    const float v[ITEMS + 12] = {
        p[0], p[1], p[2],  p[3],  p[4],  p[5],  p[6],  p[7],
        p[8], p[9], p[10], p[11], p[12], p[13], p[14], p[15],
        n0.x, n0.y, n0.z, n0.w, n1.x, n1.y, n1.z, n1.w, n2.x, n2.y, n2.z, n2.w};

    // ---- 16 sliding 13-windows.
    // L: prefix + snapshot (bitwise-exact l==0). S: sliding signed window.
    float S = 0.0f, L = 0.0f;
    float ql[ITEMS], ov4[4];
    #pragma unroll
    for (int j = 0; j < ITEMS + 12; ++j) {
        if (j < ITEMS) ql[j] = L;
        L += fmaxf(-v[j], 0.0f);
        S += v[j];
        if (j >= 13) S -= v[j - 13];
        if (j >= 12) {
            const int k = j - 12;
            const float l = L - ql[k];                   // exact over window
            const float t = S + l;                       // g = S + l
            ov4[k & 3] = (l != 0.0f) ? __fdividef(t, t + l) : 0.0f;
            if ((k & 3) == 3)                            // p consumed, neighbors done
                *(float4*)(myslot + (k - 3)) =
                    make_float4(ov4[0], ov4[1], ov4[2], ov4[3]);
        }
    }
    __syncwarp();

    // ---- coalesced scalar stores from transposed smem ----
    float* rout = out + (size_t)row * out_cols;
    if (!edge && wbase + WTILE <= out_cols) {
        #pragma unroll
        for (int m = 0; m < ITEMS; ++m) {
            const int o = lane + 32 * m;
            rout[wbase + o] = pw[SLOT * (o >> 4) + (o & 15)];
        }
    } else {
        #pragma unroll
        for (int m = 0; m < ITEMS; ++m) {
            const int o = lane + 32 * m;
            const int col = wbase + o;
            if (col < out_cols)
                rout[col] = pw[SLOT * (o >> 4) + (o & 15)];
        }
    }
}

// ---- Generic fallback for unexpected window sizes ----
__global__ __launch_bounds__(256) void rsi_generic(
    const float* __restrict__ in,
    float* __restrict__ out,
    int out_cols, int w)
{
    __shared__ float s_in[256 + MAXW + 1];
    __shared__ float s_g [256 + MAXW];
    __shared__ float s_l [256 + MAXW];

    const int row  = blockIdx.y;
    const int base = blockIdx.x * 256;
    const float* rin = in + (size_t)row * NCOLS;

    const int need_in = 256 + w + 1;
    for (int i = threadIdx.x; i < need_in; i += 256) {
        const int col = base + i;
        s_in[i] = (col < NCOLS) ? rin[col] : 0.0f;
    }
    __syncthreads();

    const int need_p = 256 + w;
    for (int i = threadIdx.x; i < need_p; i += 256) {
        const float prev = s_in[i];
        const float cur  = s_in[i + 1];
        const float p = (prev != 0.0f) ? (cur - prev) / prev : 0.0f;
        s_g[i] = fmaxf(p, 0.0f);
        s_l[i] = fmaxf(-p, 0.0f);
    }
    __syncthreads();

    const int c = base + threadIdx.x;
    if (c < out_cols) {
        float g = 0.0f, l = 0.0f;
        for (int j = 0; j < w; ++j) {
            g += s_g[threadIdx.x + j];
            l += s_l[threadIdx.x + j];
        }
        out[(size_t)row * out_cols + c] = (l != 0.0f) ? g / (g + l) : 0.0f;
    }
}

extern "C" void kernel_launch(void* const* d_in, const int* in_sizes, int n_in,
                              void* d_out, int out_size)
{
    const float* in  = (const float*)d_in[0];
    float*       out = (float*)d_out;

    const int out_cols = out_size / NROWS;   // NCOLS - (window_size - 1)
    int w = NCOLS - out_cols;

    if (w == 13) {
        dim3 grid((out_cols + TILE - 1) / TILE, NROWS);
        rsi_v13<<<grid, TPB>>>(in, out, out_cols);
    } else {
        if (w < 1)    w = 1;
        if (w > MAXW) w = MAXW;
        dim3 grid((out_cols + 255) / 256, NROWS);
        rsi_generic<<<grid, 256>>>(in, out, out_cols, w);
    }
}

// round 14
// speedup vs baseline: 1.1943x; 1.1943x over previous
#include <cuda_runtime.h>

// RSI fused single pass, v14 = v8 + conflict-free ov transpose. out[c] =
// g/(g+l) over 13-wide window of +/- relative deltas (0 if no losses).
//
// v8 skeleton byte-for-byte (best: 29.44us). ONE change, in a region v8's
// schedule doesn't touch: ov goes to a separate smem region with quad-skew
// Q(q)=q+(q>>3); writer 4 STS.128 conflict-free, reader LDS conflict-free
// (v8's read layout had 2-way conflicts: 32 wavefronts -> 16).
// Lessons: no shuffle exchange (R7/R12), no launch_bounds (R9), no
// alignment-phase stores (R10/R11), don't perturb the exchange (R13).

#define NROWS  2048
#define NCOLS  8192
#define TPB    256
#define ITEMS  16
#define WTILE  512               // outputs per warp
#define TILE   4096              // outputs per block
#define MAXW   64
#define SLOT   20                // p floats per lane slot (16 data + 4 pad)
#define PREG   (SLOT * 33)       // 32 lanes + halo slot
#define OREG   576               // 4*Q(127)+4 = 572, padded to 16B multiple

__global__ __launch_bounds__(TPB) void rsi_v14(
    const float* __restrict__ in,
    float* __restrict__ out,
    int out_cols)
{
    __shared__ __align__(16) float s_p[8 * PREG];
    __shared__ __align__(16) float s_o[8 * OREG];

    const int tid   = threadIdx.x;
    const int lane  = tid & 31;
    const int wrp   = tid >> 5;
    const int row   = blockIdx.y;
    const int wbase = blockIdx.x * TILE + wrp * WTILE;   // warp's first column
    const float* rin = in + (size_t)row * NCOLS;
    float* pw = s_p + wrp * PREG;
    float* ow = s_o + wrp * OREG;
    float* myslot = pw + SLOT * lane;
    // thread's ov base: addr(quad 4*lane+j) = 16*lane + 4*(lane>>1) + 4*j
    float* myov = ow + 16 * lane + 4 * (lane >> 1);

    const bool edge = (wbase + WTILE) >= NCOLS;          // last warp of the row

    // ---- load own 16 inputs (wbase+512 <= 8192: always in-row) ----
    const int g0 = wbase + ITEMS * lane;
    const float4 xA = *(const float4*)(rin + g0);
    const float4 xB = *(const float4*)(rin + g0 + 4);
    const float4 xC = *(const float4*)(rin + g0 + 8);
    const float4 xD = *(const float4*)(rin + g0 + 12);

    // x[g0+16]: neighbor's first x via shuffle; lane 31 loads (guarded)
    float x16 = __shfl_down_sync(0xffffffffu, xA.x, 1);
    if (lane == 31)
        x16 = (!edge) ? rin[g0 + 16] : 0.0f;

    // halo x: lanes 0..12 load x[wbase+512+lane] (zero past row end)
    float xe = 0.0f;
    if (lane < 13) {
        const int ge = wbase + WTILE + lane;
        xe = (ge < NCOLS) ? rin[ge] : 0.0f;
    }
    const float xen = __shfl_down_sync(0xffffffffu, xe, 1);

    // ---- own 16 p-values ----
    const float xs[17] = {xA.x, xA.y, xA.z, xA.w, xB.x, xB.y, xB.z, xB.w,
                          xC.x, xC.y, xC.z, xC.w, xD.x, xD.y, xD.z, xD.w, x16};
    float p[ITEMS];
    #pragma unroll
    for (int c = 0; c < ITEMS; ++c) {
        const float prev = xs[c];
        p[c] = (prev != 0.0f) ? __fdividef(xs[c + 1] - prev, prev) : 0.0f;
    }

    // ---- publish p (stride-20, conflict-free STS.128; all 4 per R13) ----
    *(float4*)(myslot)      = make_float4(p[0],  p[1],  p[2],  p[3]);
    *(float4*)(myslot + 4)  = make_float4(p[4],  p[5],  p[6],  p[7]);
    *(float4*)(myslot + 8)  = make_float4(p[8],  p[9],  p[10], p[11]);
    *(float4*)(myslot + 12) = make_float4(p[12], p[13], p[14], p[15]);
    if (lane < 12) {                                     // halo p -> slot 32
        const float pe = (xe != 0.0f) ? __fdividef(xen - xe, xe) : 0.0f;
        pw[SLOT * 32 + lane] = pe;
    }
    __syncwarp();

    // ---- fetch 12 neighbor p-values (lane 31 hits halo slot 32) ----
    const float* nb = pw + SLOT * (lane + 1);
    const float4 n0 = *(const float4*)(nb);
    const float4 n1 = *(const float4*)(nb + 4);
    const float4 n2 = *(const float4*)(nb + 8);

    const float v[ITEMS + 12] = {
        p[0], p[1], p[2],  p[3],  p[4],  p[5],  p[6],  p[7],
        p[8], p[9], p[10], p[11], p[12], p[13], p[14], p[15],
        n0.x, n0.y, n0.z, n0.w, n1.x, n1.y, n1.z, n1.w, n2.x, n2.y, n2.z, n2.w};

    // ---- 16 sliding 13-windows.
    // L: prefix + snapshot (bitwise-exact l==0). S: sliding signed window.
    float S = 0.0f, L = 0.0f;
    float ql[ITEMS], ov4[4];
    #pragma unroll
    for (int j = 0; j < ITEMS + 12; ++j) {
        if (j < ITEMS) ql[j] = L;
        L += fmaxf(-v[j], 0.0f);
        S += v[j];
        if (j >= 13) S -= v[j - 13];
        if (j >= 12) {
            const int k = j - 12;
            const float l = L - ql[k];                   // exact over window
            const float t = S + l;                       // g = S + l
            ov4[k & 3] = (l != 0.0f) ? __fdividef(t, t + l) : 0.0f;
            if ((k & 3) == 3)                            // separate ov region
                *(float4*)(myov + (k - 3)) =             // quad j=(k-3)>>2 at +4j
                    make_float4(ov4[0], ov4[1], ov4[2], ov4[3]);
        }
    }
    __syncwarp();

    // ---- coalesced scalar stores, conflict-free quad-skew reads ----
    float* rout = out + (size_t)row * out_cols;
    if (!edge && wbase + WTILE <= out_cols) {
        #pragma unroll
        for (int m = 0; m < ITEMS; ++m) {
            const int o = lane + 32 * m;
            rout[wbase + o] = ow[4 * ((o >> 2) + m) + (o & 3)];
        }
    } else {
        #pragma unroll
        for (int m = 0; m < ITEMS; ++m) {
            const int o = lane + 32 * m;
            const int col = wbase + o;
            if (col < out_cols)
                rout[col] = ow[4 * ((o >> 2) + m) + (o & 3)];
        }
    }
}

// ---- Generic fallback for unexpected window sizes ----
__global__ __launch_bounds__(256) void rsi_generic(
    const float* __restrict__ in,
    float* __restrict__ out,
    int out_cols, int w)
{
    __shared__ float s_in[256 + MAXW + 1];
    __shared__ float s_g [256 + MAXW];
    __shared__ float s_l [256 + MAXW];

    const int row  = blockIdx.y;
    const int base = blockIdx.x * 256;
    const float* rin = in + (size_t)row * NCOLS;

    const int need_in = 256 + w + 1;
    for (int i = threadIdx.x; i < need_in; i += 256) {
        const int col = base + i;
        s_in[i] = (col < NCOLS) ? rin[col] : 0.0f;
    }
    __syncthreads();

    const int need_p = 256 + w;
    for (int i = threadIdx.x; i < need_p; i += 256) {
        const float prev = s_in[i];
        const float cur  = s_in[i + 1];
        const float p = (prev != 0.0f) ? (cur - prev) / prev : 0.0f;
        s_g[i] = fmaxf(p, 0.0f);
        s_l[i] = fmaxf(-p, 0.0f);
    }
    __syncthreads();

    const int c = base + threadIdx.x;
    if (c < out_cols) {
        float g = 0.0f, l = 0.0f;
        for (int j = 0; j < w; ++j) {
            g += s_g[threadIdx.x + j];
            l += s_l[threadIdx.x + j];
        }
        out[(size_t)row * out_cols + c] = (l != 0.0f) ? g / (g + l) : 0.0f;
    }
}

extern "C" void kernel_launch(void* const* d_in, const int* in_sizes, int n_in,
                              void* d_out, int out_size)
{
    const float* in  = (const float*)d_in[0];
    float*       out = (float*)d_out;

    const int out_cols = out_size / NROWS;   // NCOLS - (window_size - 1)
    int w = NCOLS - out_cols;

    if (w == 13) {
        dim3 grid((out_cols + TILE - 1) / TILE, NROWS);
        rsi_v14<<<grid, TPB>>>(in, out, out_cols);
    } else {
        if (w < 1)    w = 1;
        if (w > MAXW) w = MAXW;
        dim3 grid((out_cols + 255) / 256, NROWS);
        rsi_generic<<<grid, 256>>>(in, out, out_cols, w);
    }
}

// round 15
// speedup vs baseline: 1.2845x; 1.0755x over previous
#include <cuda_runtime.h>

// RSI fused single pass, v15 = v8 champion + cache-policy hints only.
// out[c] = g/(g+l) over 13-wide window of +/- relative deltas (0 if no
// losses in window).
//
// v8 skeleton byte-for-byte (best: 29.44us wall / 26.24us ncu). Only change:
// __ldcs on the 4 main input loads (read-once) and __stcs on output stores
// (write-once, never re-read) — same instructions, same schedule, only
// cache-op bits differ. R9-R14 showed every structural deviation from v8
// ties or regresses (balanced profile: issue 75 / L1 64 / DRAM 42).

#define NROWS  2048
#define NCOLS  8192
#define TPB    256
#define ITEMS  16
#define WTILE  512               // outputs per warp
#define TILE   4096              // outputs per block
#define MAXW   64
#define SLOT   20                // smem floats per lane slot (16 data + 4 pad)
#define PREG   (SLOT * 33)       // 32 lanes + halo slot

__global__ __launch_bounds__(TPB) void rsi_v15(
    const float* __restrict__ in,
    float* __restrict__ out,
    int out_cols)
{
    __shared__ __align__(16) float s_p[8 * PREG];

    const int tid   = threadIdx.x;
    const int lane  = tid & 31;
    const int wrp   = tid >> 5;
    const int row   = blockIdx.y;
    const int wbase = blockIdx.x * TILE + wrp * WTILE;   // warp's first column
    const float* rin = in + (size_t)row * NCOLS;
    float* pw = s_p + wrp * PREG;
    float* myslot = pw + SLOT * lane;

    const bool edge = (wbase + WTILE) >= NCOLS;          // last warp of the row

    // ---- load own 16 inputs (wbase+512 <= 8192: always in-row) ----
    const int g0 = wbase + ITEMS * lane;
    const float4 xA = __ldcs((const float4*)(rin + g0));
    const float4 xB = __ldcs((const float4*)(rin + g0 + 4));
    const float4 xC = __ldcs((const float4*)(rin + g0 + 8));
    const float4 xD = __ldcs((const float4*)(rin + g0 + 12));

    // x[g0+16]: neighbor's first x via shuffle; lane 31 loads (guarded)
    float x16 = __shfl_down_sync(0xffffffffu, xA.x, 1);
    if (lane == 31)
        x16 = (!edge) ? rin[g0 + 16] : 0.0f;

    // halo x: lanes 0..12 load x[wbase+512+lane] (zero past row end)
    float xe = 0.0f;
    if (lane < 13) {
        const int ge = wbase + WTILE + lane;
        xe = (ge < NCOLS) ? rin[ge] : 0.0f;
    }
    const float xen = __shfl_down_sync(0xffffffffu, xe, 1);

    // ---- own 16 p-values ----
    const float xs[17] = {xA.x, xA.y, xA.z, xA.w, xB.x, xB.y, xB.z, xB.w,
                          xC.x, xC.y, xC.z, xC.w, xD.x, xD.y, xD.z, xD.w, x16};
    float p[ITEMS];
    #pragma unroll
    for (int c = 0; c < ITEMS; ++c) {
        const float prev = xs[c];
        p[c] = (prev != 0.0f) ? __fdividef(xs[c + 1] - prev, prev) : 0.0f;
    }

    // ---- publish p (stride-20, conflict-free STS.128) ----
    *(float4*)(myslot)      = make_float4(p[0],  p[1],  p[2],  p[3]);
    *(float4*)(myslot + 4)  = make_float4(p[4],  p[5],  p[6],  p[7]);
    *(float4*)(myslot + 8)  = make_float4(p[8],  p[9],  p[10], p[11]);
    *(float4*)(myslot + 12) = make_float4(p[12], p[13], p[14], p[15]);
    if (lane < 12) {                                     // halo p -> slot 32
        const float pe = (xe != 0.0f) ? __fdividef(xen - xe, xe) : 0.0f;
        pw[SLOT * 32 + lane] = pe;
    }
    __syncwarp();

    // ---- fetch 12 neighbor p-values (lane 31 hits halo slot 32) ----
    const float* nb = pw + SLOT * (lane + 1);
    const float4 n0 = *(const float4*)(nb);
    const float4 n1 = *(const float4*)(nb + 4);
    const float4 n2 = *(const float4*)(nb + 8);
    __syncwarp();                                        // reads done before overwrite

    const float v[ITEMS + 12] = {
        p[0], p[1], p[2],  p[3],  p[4],  p[5],  p[6],  p[7],
        p[8], p[9], p[10], p[11], p[12], p[13], p[14], p[15],
        n0.x, n0.y, n0.z, n0.w, n1.x, n1.y, n1.z, n1.w, n2.x, n2.y, n2.z, n2.w};

    // ---- 16 sliding 13-windows.
    // L: prefix + snapshot (bitwise-exact l==0). S: sliding signed window.
    float S = 0.0f, L = 0.0f;
    float ql[ITEMS], ov4[4];
    #pragma unroll
    for (int j = 0; j < ITEMS + 12; ++j) {
        if (j < ITEMS) ql[j] = L;
        L += fmaxf(-v[j], 0.0f);
        S += v[j];
        if (j >= 13) S -= v[j - 13];
        if (j >= 12) {
            const int k = j - 12;
            const float l = L - ql[k];                   // exact over window
            const float t = S + l;                       // g = S + l
            ov4[k & 3] = (l != 0.0f) ? __fdividef(t, t + l) : 0.0f;
            if ((k & 3) == 3)                            // p consumed, neighbors done
                *(float4*)(myslot + (k - 3)) =
                    make_float4(ov4[0], ov4[1], ov4[2], ov4[3]);
        }
    }
    __syncwarp();

    // ---- coalesced scalar streaming stores from transposed smem ----
    float* rout = out + (size_t)row * out_cols;
    if (!edge && wbase + WTILE <= out_cols) {
        #pragma unroll
        for (int m = 0; m < ITEMS; ++m) {
            const int o = lane + 32 * m;
            __stcs(rout + wbase + o, pw[SLOT * (o >> 4) + (o & 15)]);
        }
    } else {
        #pragma unroll
        for (int m = 0; m < ITEMS; ++m) {
            const int o = lane + 32 * m;
            const int col = wbase + o;
            if (col < out_cols)
                __stcs(rout + col, pw[SLOT * (o >> 4) + (o & 15)]);
        }
    }
}

// ---- Generic fallback for unexpected window sizes ----
__global__ __launch_bounds__(256) void rsi_generic(
    const float* __restrict__ in,
    float* __restrict__ out,
    int out_cols, int w)
{
    __shared__ float s_in[256 + MAXW + 1];
    __shared__ float s_g [256 + MAXW];
    __shared__ float s_l [256 + MAXW];

    const int row  = blockIdx.y;
    const int base = blockIdx.x * 256;
    const float* rin = in + (size_t)row * NCOLS;

    const int need_in = 256 + w + 1;
    for (int i = threadIdx.x; i < need_in; i += 256) {
        const int col = base + i;
        s_in[i] = (col < NCOLS) ? rin[col] : 0.0f;
    }
    __syncthreads();

    const int need_p = 256 + w;
    for (int i = threadIdx.x; i < need_p; i += 256) {
        const float prev = s_in[i];
        const float cur  = s_in[i + 1];
        const float p = (prev != 0.0f) ? (cur - prev) / prev : 0.0f;
        s_g[i] = fmaxf(p, 0.0f);
        s_l[i] = fmaxf(-p, 0.0f);
    }
    __syncthreads();

    const int c = base + threadIdx.x;
    if (c < out_cols) {
        float g = 0.0f, l = 0.0f;
        for (int j = 0; j < w; ++j) {
            g += s_g[threadIdx.x + j];
            l += s_l[threadIdx.x + j];
        }
        out[(size_t)row * out_cols + c] = (l != 0.0f) ? g / (g + l) : 0.0f;
    }
}

extern "C" void kernel_launch(void* const* d_in, const int* in_sizes, int n_in,
                              void* d_out, int out_size)
{
    const float* in  = (const float*)d_in[0];
    float*       out = (float*)d_out;

    const int out_cols = out_size / NROWS;   // NCOLS - (window_size - 1)
    int w = NCOLS - out_cols;

    if (w == 13) {
        dim3 grid((out_cols + TILE - 1) / TILE, NROWS);
        rsi_v15<<<grid, TPB>>>(in, out, out_cols);
    } else {
        if (w < 1)    w = 1;
        if (w > MAXW) w = MAXW;
        dim3 grid((out_cols + 255) / 256, NROWS);
        rsi_generic<<<grid, 256>>>(in, out, out_cols, w);
    }
}